// round 4
// baseline (speedup 1.0000x reference)
#include <cuda_runtime.h>
#include <cuda_bf16.h>
#include <math.h>
#include <stdint.h>

#define BB 2
#define TT 2048
#define EE 768
#define HH 12
#define DD 64
#define MM (BB*TT)      // 4096 tokens
#define FFN (4*EE)      // 3072
#define QKVN (3*EE)     // 2304

// ---------------- scratch (__device__ globals; no allocs allowed) ----------------
__device__ float g_qkv[MM*QKVN];           // fused q|k|v fp32
__device__ float g_x1 [MM*EE];             // attn out + resid (fp32)
__device__ __nv_bfloat16 g_h1h[MM*EE],  g_h1l[MM*EE];
__device__ __nv_bfloat16 g_h2h[MM*EE],  g_h2l[MM*EE];
__device__ __nv_bfloat16 g_cxh[MM*EE],  g_cxl[MM*EE];
__device__ __nv_bfloat16 g_f1h[MM*FFN], g_f1l[MM*FFN];
// transposed+split weights, [N,K] layout
__device__ __nv_bfloat16 g_wqkvh[QKVN*EE], g_wqkvl[QKVN*EE];
__device__ __nv_bfloat16 g_woh[EE*EE],     g_wol[EE*EE];
__device__ __nv_bfloat16 g_w1h[FFN*EE],    g_w1l[FFN*EE];
__device__ __nv_bfloat16 g_w2h[EE*FFN],    g_w2l[EE*FFN];

// ---------------- PTX helpers ----------------
__device__ __forceinline__ uint32_t smem_u32(const void* p) {
    uint32_t a;
    asm("{ .reg .u64 t; cvta.to.shared.u64 t, %1; cvt.u32.u64 %0, t; }" : "=r"(a) : "l"(p));
    return a;
}

#define CP_ASYNC16(dst, src) \
    asm volatile("cp.async.cg.shared.global [%0], [%1], 16;" :: "r"(dst), "l"(src))
#define CP_COMMIT() asm volatile("cp.async.commit_group;" ::: "memory")
#define CP_WAIT(n)  asm volatile("cp.async.wait_group %0;" :: "n"(n) : "memory")

#define LDSM4(r0, r1, r2, r3, addr) \
    asm volatile("ldmatrix.sync.aligned.m8n8.x4.shared.b16 {%0,%1,%2,%3}, [%4];" \
        : "=r"(r0), "=r"(r1), "=r"(r2), "=r"(r3) : "r"(addr))

#define MMA16816(d, a, b0, b1) \
    asm volatile("mma.sync.aligned.m16n8k16.row.col.f32.bf16.bf16.f32 " \
        "{%0,%1,%2,%3}, {%4,%5,%6,%7}, {%8,%9}, {%0,%1,%2,%3};" \
        : "+f"((d)[0]), "+f"((d)[1]), "+f"((d)[2]), "+f"((d)[3]) \
        : "r"((a)[0]), "r"((a)[1]), "r"((a)[2]), "r"((a)[3]), "r"(b0), "r"(b1))

__device__ __forceinline__ void split2(float x, __nv_bfloat16& h, __nv_bfloat16& l) {
    h = __float2bfloat16(x);
    l = __float2bfloat16(x - __bfloat162float(h));
}

// ============================================================
// Weight transpose + hi/lo split: src[K,N] fp32 -> dst[N,K] bf16 x2
// ============================================================
__global__ __launch_bounds__(256) void tsplit_kernel(
    const float* __restrict__ src, __nv_bfloat16* __restrict__ dh,
    __nv_bfloat16* __restrict__ dl, int K, int N)
{
    __shared__ float t[32][33];
    int n0 = blockIdx.x * 32, k0 = blockIdx.y * 32;
    int tx = threadIdx.x & 31, ty = threadIdx.x >> 5;
    #pragma unroll
    for (int j = 0; j < 32; j += 8)
        t[ty + j][tx] = src[(size_t)(k0 + ty + j) * N + n0 + tx];
    __syncthreads();
    #pragma unroll
    for (int j = 0; j < 32; j += 8) {
        float v = t[tx][ty + j];
        __nv_bfloat16 h, l; split2(v, h, l);
        size_t o = (size_t)(n0 + ty + j) * K + k0 + tx;
        dh[o] = h; dl[o] = l;
    }
}

// ============================================================
// LayerNorm (ddof=1) -> bf16 hi/lo outputs
// ============================================================
__global__ __launch_bounds__(256) void ln_kernel(
    const float* __restrict__ x, const float* __restrict__ sc,
    const float* __restrict__ sh, __nv_bfloat16* __restrict__ oh,
    __nv_bfloat16* __restrict__ ol)
{
    int row = blockIdx.x;
    int t = threadIdx.x;
    const float* xr = x + (size_t)row * EE;
    float v0 = xr[t], v1 = xr[t + 256], v2 = xr[t + 512];
    float s = v0 + v1 + v2, ss = v0*v0 + v1*v1 + v2*v2;
    #pragma unroll
    for (int o = 16; o; o >>= 1) {
        s  += __shfl_xor_sync(0xffffffffu, s,  o);
        ss += __shfl_xor_sync(0xffffffffu, ss, o);
    }
    __shared__ float red[2][8];
    __shared__ float mean_s, rstd_s;
    int w = t >> 5, ln = t & 31;
    if (ln == 0) { red[0][w] = s; red[1][w] = ss; }
    __syncthreads();
    if (t == 0) {
        float S = 0.f, SS = 0.f;
        #pragma unroll
        for (int i = 0; i < 8; i++) { S += red[0][i]; SS += red[1][i]; }
        float mean = S / (float)EE;
        float var  = (SS - S * mean) / (float)(EE - 1);
        mean_s = mean;
        rstd_s = rsqrtf(var + 1e-5f);
    }
    __syncthreads();
    float mean = mean_s, r = rstd_s;
    size_t base = (size_t)row * EE;
    #pragma unroll
    for (int u = 0; u < 3; u++) {
        int c = t + u * 256;
        float vv = (u == 0 ? v0 : (u == 1 ? v1 : v2));
        float y = sc[c] * (vv - mean) * r + sh[c];
        __nv_bfloat16 h, l; split2(y, h, l);
        oh[base + c] = h; ol[base + c] = l;
    }
}

// ============================================================
// mma.sync bf16 GEMM (3-way hi/lo split, fp32 accumulate)
// C[M,Nout] = A[M,K] @ B[Nout,K]^T
// CTA tile 128 x BN, K-chunk 64, cp.async 2-stage, 256 threads.
// Warps 4(M) x 2(N); warp tile 32 x BN/2; mma.m16n8k16.
// EPI: 0 = fp32 | 1 = +bias +resid fp32 | 2 = +bias, GELU, bf16 hi/lo
// ============================================================
template<int EPI, int BN>
__global__ __launch_bounds__(256, 1) void mma_gemm(
    const __nv_bfloat16* __restrict__ Ahi, const __nv_bfloat16* __restrict__ Alo,
    const __nv_bfloat16* __restrict__ Bhi, const __nv_bfloat16* __restrict__ Blo,
    int K, int ldc,
    float* __restrict__ C,
    __nv_bfloat16* __restrict__ Chi, __nv_bfloat16* __restrict__ Clo,
    const float* __restrict__ bias, const float* __restrict__ resid)
{
    constexpr int WN = BN / 2;           // warp N extent
    constexpr int NG = WN / 16;          // n16 ldsm groups per warp
    constexpr int BSZ = BN * 128;        // one B buffer (bytes)
    constexpr int STAGE = 32768 + 2 * BSZ;  // Ah+Al + Bh+Bl

    extern __shared__ char smc[];
    const int tid  = threadIdx.x;
    const int wid  = tid >> 5, lane = tid & 31;
    const int wm   = wid >> 1, wn = wid & 1;
    const uint32_t sbase = smem_u32(smc);
    const int rowBase = blockIdx.y * 128;
    const int colBase = blockIdx.x * BN;
    const int nc = K / 64;

    // ---- async loader: gmem(bf16) -> swizzled smem stage ----
    auto load_stage = [&](int ch, int s) {
        const int kc = ch * 64;
        const uint32_t st = sbase + s * STAGE;
        #pragma unroll
        for (int j = 0; j < 4; j++) {                 // A: 128 rows x 8 chunks
            int i = tid + j * 256;
            int r = i >> 3, c = i & 7;
            uint32_t so = (uint32_t)(r * 128 + ((c ^ (r & 7)) * 16));
            size_t go = (size_t)(rowBase + r) * K + kc + c * 8;
            CP_ASYNC16(st + so,         Ahi + go);
            CP_ASYNC16(st + 16384 + so, Alo + go);
        }
        #pragma unroll
        for (int j = 0; j < BN / 32; j++) {           // B: BN rows x 8 chunks
            int i = tid + j * 256;
            int r = i >> 3, c = i & 7;
            uint32_t so = (uint32_t)(r * 128 + ((c ^ (r & 7)) * 16));
            size_t go = (size_t)(colBase + r) * K + kc + c * 8;
            CP_ASYNC16(st + 32768 + so,       Bhi + go);
            CP_ASYNC16(st + 32768 + BSZ + so, Blo + go);
        }
    };

    float acc[2][WN / 8][4];
    #pragma unroll
    for (int mi = 0; mi < 2; mi++)
        #pragma unroll
        for (int nj = 0; nj < WN / 8; nj++)
            #pragma unroll
            for (int q = 0; q < 4; q++) acc[mi][nj][q] = 0.f;

    // per-lane ldmatrix address pieces
    const uint32_t aoff = (uint32_t)((wm * 32 + (lane & 15)) * 128);
    const uint32_t boff = (uint32_t)((wn * WN + (lane & 15)) * 128);
    const int csel = lane >> 4;          // chunk select (0/1)
    const int cxor = lane & 7;           // swizzle xor

    load_stage(0, 0); CP_COMMIT();

    for (int ch = 0; ch < nc; ch++) {
        if (ch + 1 < nc) { load_stage(ch + 1, (ch + 1) & 1); CP_COMMIT(); CP_WAIT(1); }
        else             { CP_WAIT(0); }
        __syncthreads();

        const uint32_t stg = sbase + (ch & 1) * STAGE;
        #pragma unroll
        for (int p = 0; p < 3; p++) {    // AhBh, AhBl, AlBh
            const uint32_t Ab = stg + (p == 2 ? 16384 : 0);
            const uint32_t Bb = stg + 32768 + (p == 1 ? BSZ : 0);
            #pragma unroll
            for (int k16 = 0; k16 < 4; k16++) {
                const uint32_t csw = (uint32_t)(((k16 * 2 + csel) ^ cxor) * 16);
                uint32_t a[2][4];
                LDSM4(a[0][0], a[0][1], a[0][2], a[0][3], Ab + aoff + csw);
                LDSM4(a[1][0], a[1][1], a[1][2], a[1][3], Ab + aoff + 2048 + csw);
                #pragma unroll
                for (int ng = 0; ng < NG; ng++) {
                    uint32_t b0, b1, b2, b3;
                    LDSM4(b0, b1, b2, b3, Bb + boff + ng * 2048 + csw);
                    MMA16816(acc[0][2 * ng],     a[0], b0, b2);
                    MMA16816(acc[0][2 * ng + 1], a[0], b1, b3);
                    MMA16816(acc[1][2 * ng],     a[1], b0, b2);
                    MMA16816(acc[1][2 * ng + 1], a[1], b1, b3);
                }
            }
        }
        __syncthreads();
    }

    // ---- epilogue ----
    const int lr = lane >> 2, lc = (lane & 3) * 2;
    #pragma unroll
    for (int mi = 0; mi < 2; mi++) {
        #pragma unroll
        for (int nj = 0; nj < WN / 8; nj++) {
            int r0 = rowBase + wm * 32 + mi * 16 + lr;
            int c0 = colBase + wn * WN + nj * 8 + lc;
            float* d = acc[mi][nj];
            #pragma unroll
            for (int half = 0; half < 2; half++) {
                int r = r0 + half * 8;
                float v0 = d[half * 2], v1 = d[half * 2 + 1];
                if (EPI >= 1) { v0 += bias[c0]; v1 += bias[c0 + 1]; }
                if (EPI == 2) {
                    float u0 = v0, u1 = v1;
                    v0 = 0.5f * u0 * (1.f + tanhf(0.7978845608028654f * (u0 + 0.044715f * u0 * u0 * u0)));
                    v1 = 0.5f * u1 * (1.f + tanhf(0.7978845608028654f * (u1 + 0.044715f * u1 * u1 * u1)));
                }
                if (EPI == 1) {
                    v0 += resid[(size_t)r * ldc + c0];
                    v1 += resid[(size_t)r * ldc + c0 + 1];
                }
                if (EPI == 2) {
                    __nv_bfloat16 h0, l0, h1, l1;
                    split2(v0, h0, l0); split2(v1, h1, l1);
                    *(__nv_bfloat162*)&Chi[(size_t)r * ldc + c0] = __nv_bfloat162(h0, h1);
                    *(__nv_bfloat162*)&Clo[(size_t)r * ldc + c0] = __nv_bfloat162(l0, l1);
                } else {
                    *(float2*)&C[(size_t)r * ldc + c0] = make_float2(v0, v1);
                }
            }
        }
    }
}

// ============================================================
// Causal flash attention, fp32, fused-QKV input, hi/lo ctx output
// ============================================================
__global__ __launch_bounds__(128) void attn_kernel(
    const float* __restrict__ qkv, __nv_bfloat16* __restrict__ cxh,
    __nv_bfloat16* __restrict__ cxl)
{
    __shared__ float Qt[64][128];
    __shared__ float Ks[32][64];
    __shared__ float Vs[32][64];

    int tid = threadIdx.x;
    int bh = blockIdx.y;
    int b = bh / HH, h = bh % HH;
    int q0 = blockIdx.x * 128;
    const float* qb = qkv + (size_t)b * TT * QKVN + h * DD;
    const float* kb = qb + EE;
    const float* vb = qb + 2 * EE;
    const float SC = 0.125f * 1.4426950408889634f;

    for (int i = tid; i < 128 * 64; i += 128) {
        int rr = i >> 6, dd = i & 63;
        Qt[dd][rr] = qb[(size_t)(q0 + rr) * QKVN + dd] * SC;
    }

    float O[64];
    #pragma unroll
    for (int d = 0; d < 64; d++) O[d] = 0.f;
    float m = -1e30f, l = 0.f;
    int qi = q0 + tid;
    int ktiles = q0 / 32 + 4;

    for (int jt = 0; jt < ktiles; ++jt) {
        int k0 = jt * 32;
        __syncthreads();
        for (int i = tid; i < 32 * 64; i += 128) {
            int rr = i >> 6, dd = i & 63;
            Ks[rr][dd] = kb[(size_t)(k0 + rr) * QKVN + dd];
            Vs[rr][dd] = vb[(size_t)(k0 + rr) * QKVN + dd];
        }
        __syncthreads();

        float s[32];
        #pragma unroll
        for (int c = 0; c < 32; c++) s[c] = 0.f;
        #pragma unroll
        for (int d0 = 0; d0 < 64; d0 += 4) {
            float q0v = Qt[d0][tid],     q1v = Qt[d0 + 1][tid];
            float q2v = Qt[d0 + 2][tid], q3v = Qt[d0 + 3][tid];
            #pragma unroll
            for (int c = 0; c < 32; c++) {
                const float4 kv = *(const float4*)&Ks[c][d0];
                s[c] += q0v * kv.x + q1v * kv.y + q2v * kv.z + q3v * kv.w;
            }
        }

        float mloc = -1e30f;
        #pragma unroll
        for (int c = 0; c < 32; c++) {
            if (k0 + c > qi) s[c] = -1e30f;
            mloc = fmaxf(mloc, s[c]);
        }
        float mn  = fmaxf(m, mloc);
        float fac = exp2f(m - mn);
        l *= fac;
        #pragma unroll
        for (int d = 0; d < 64; d++) O[d] *= fac;
        #pragma unroll
        for (int c = 0; c < 32; c++) {
            float p = exp2f(s[c] - mn);
            l += p;
            #pragma unroll
            for (int d0 = 0; d0 < 64; d0 += 4) {
                const float4 vv = *(const float4*)&Vs[c][d0];
                O[d0]     += p * vv.x;
                O[d0 + 1] += p * vv.y;
                O[d0 + 2] += p * vv.z;
                O[d0 + 3] += p * vv.w;
            }
        }
        m = mn;
    }

    float inv = 1.f / l;
    size_t ob = (size_t)(b * TT + q0 + tid) * EE + h * DD;
    #pragma unroll
    for (int d = 0; d < 64; d++) {
        __nv_bfloat16 hh, ll;
        split2(O[d] * inv, hh, ll);
        cxh[ob + d] = hh; cxl[ob + d] = ll;
    }
}

// ============================================================
extern "C" void kernel_launch(void* const* d_in, const int* in_sizes, int n_in,
                              void* d_out, int out_size)
{
    const float* x   = (const float*)d_in[0];
    const float* wq  = (const float*)d_in[1];
    const float* wk  = (const float*)d_in[2];
    const float* wv  = (const float*)d_in[3];
    const float* wo  = (const float*)d_in[4];
    const float* bo  = (const float*)d_in[5];
    const float* l1s = (const float*)d_in[6];
    const float* l1b = (const float*)d_in[7];
    const float* l2s = (const float*)d_in[8];
    const float* l2b = (const float*)d_in[9];
    const float* w1  = (const float*)d_in[10];
    const float* b1  = (const float*)d_in[11];
    const float* w2  = (const float*)d_in[12];
    const float* b2  = (const float*)d_in[13];
    float* out = (float*)d_out;

    float *qkv, *x1;
    __nv_bfloat16 *h1h,*h1l,*h2h,*h2l,*cxh,*cxl,*f1h,*f1l;
    __nv_bfloat16 *wqkvh,*wqkvl,*woh,*wol,*w1h,*w1l,*w2h,*w2l;
    cudaGetSymbolAddress((void**)&qkv, g_qkv);
    cudaGetSymbolAddress((void**)&x1,  g_x1);
    cudaGetSymbolAddress((void**)&h1h, g_h1h); cudaGetSymbolAddress((void**)&h1l, g_h1l);
    cudaGetSymbolAddress((void**)&h2h, g_h2h); cudaGetSymbolAddress((void**)&h2l, g_h2l);
    cudaGetSymbolAddress((void**)&cxh, g_cxh); cudaGetSymbolAddress((void**)&cxl, g_cxl);
    cudaGetSymbolAddress((void**)&f1h, g_f1h); cudaGetSymbolAddress((void**)&f1l, g_f1l);
    cudaGetSymbolAddress((void**)&wqkvh, g_wqkvh); cudaGetSymbolAddress((void**)&wqkvl, g_wqkvl);
    cudaGetSymbolAddress((void**)&woh, g_woh); cudaGetSymbolAddress((void**)&wol, g_wol);
    cudaGetSymbolAddress((void**)&w1h, g_w1h); cudaGetSymbolAddress((void**)&w1l, g_w1l);
    cudaGetSymbolAddress((void**)&w2h, g_w2h); cudaGetSymbolAddress((void**)&w2l, g_w2l);

    constexpr int SMEM256 = 2 * (32768 + 2 * 256 * 128);  // 196608
    constexpr int SMEM128 = 2 * (32768 + 2 * 128 * 128);  // 131072
    cudaFuncSetAttribute(mma_gemm<0,256>, cudaFuncAttributeMaxDynamicSharedMemorySize, SMEM256);
    cudaFuncSetAttribute(mma_gemm<2,256>, cudaFuncAttributeMaxDynamicSharedMemorySize, SMEM256);
    cudaFuncSetAttribute(mma_gemm<1,128>, cudaFuncAttributeMaxDynamicSharedMemorySize, SMEM128);

    // ---- prep: transpose + split weights ----
    dim3 tEE(EE/32, EE/32);
    tsplit_kernel<<<tEE, 256>>>(wq, wqkvh,           wqkvl,           EE, EE);
    tsplit_kernel<<<tEE, 256>>>(wk, wqkvh + EE*EE,   wqkvl + EE*EE,   EE, EE);
    tsplit_kernel<<<tEE, 256>>>(wv, wqkvh + 2*EE*EE, wqkvl + 2*EE*EE, EE, EE);
    tsplit_kernel<<<tEE, 256>>>(wo, woh, wol, EE, EE);
    tsplit_kernel<<<dim3(FFN/32, EE/32), 256>>>(w1, w1h, w1l, EE, FFN);
    tsplit_kernel<<<dim3(EE/32, FFN/32), 256>>>(w2, w2h, w2l, FFN, EE);

    // ---- LN1 -> h1 (bf16 hi/lo) ----
    ln_kernel<<<MM, 256>>>(x, l1s, l1b, h1h, h1l);
    // ---- fused QKV GEMM: [M,768] x [2304,768]^T -> fp32 qkv ----
    mma_gemm<0,256><<<dim3(QKVN/256, MM/128), 256, SMEM256>>>(
        h1h, h1l, wqkvh, wqkvl, EE, QKVN, qkv, nullptr, nullptr, nullptr, nullptr);
    // ---- attention -> ctx (bf16 hi/lo) ----
    attn_kernel<<<dim3(TT/128, BB*HH), 128>>>(qkv, cxh, cxl);
    // ---- WO proj + bias + resid(x) -> x1 fp32 ----
    mma_gemm<1,128><<<dim3(EE/128, MM/128), 256, SMEM128>>>(
        cxh, cxl, woh, wol, EE, EE, x1, nullptr, nullptr, bo, x);
    // ---- LN2 -> h2 (bf16 hi/lo) ----
    ln_kernel<<<MM, 256>>>(x1, l2s, l2b, h2h, h2l);
    // ---- MLP up + GELU -> f1 (bf16 hi/lo) ----
    mma_gemm<2,256><<<dim3(FFN/256, MM/128), 256, SMEM256>>>(
        h2h, h2l, w1h, w1l, EE, FFN, nullptr, f1h, f1l, b1, nullptr);
    // ---- MLP down + bias + resid(x1) -> out ----
    mma_gemm<1,128><<<dim3(EE/128, MM/128), 256, SMEM128>>>(
        f1h, f1l, w2h, w2l, FFN, EE, out, nullptr, nullptr, b2, x1);
}

// round 6
// speedup vs baseline: 1.6525x; 1.6525x over previous
#include <cuda_runtime.h>
#include <cuda_bf16.h>
#include <math.h>
#include <stdint.h>

#define BB 2
#define TT 2048
#define EE 768
#define HH 12
#define DD 64
#define MM (BB*TT)      // 4096 tokens
#define FFN (4*EE)      // 3072
#define QKVN (3*EE)     // 2304

// ---------------- scratch (__device__ globals; no allocs allowed) ----------------
__device__ float g_qkv[MM*QKVN];           // fused q|k|v fp32
__device__ float g_x1 [MM*EE];             // attn out + resid (fp32)
__device__ __nv_bfloat16 g_h1h[MM*EE],  g_h1l[MM*EE];
__device__ __nv_bfloat16 g_h2h[MM*EE],  g_h2l[MM*EE];
__device__ __nv_bfloat16 g_cxh[MM*EE],  g_cxl[MM*EE];
__device__ __nv_bfloat16 g_f1h[MM*FFN], g_f1l[MM*FFN];
// transposed+split weights, [N,K] layout
__device__ __nv_bfloat16 g_wqkvh[QKVN*EE], g_wqkvl[QKVN*EE];
__device__ __nv_bfloat16 g_woh[EE*EE],     g_wol[EE*EE];
__device__ __nv_bfloat16 g_w1h[FFN*EE],    g_w1l[FFN*EE];
__device__ __nv_bfloat16 g_w2h[EE*FFN],    g_w2l[EE*FFN];

// ---------------- PTX helpers ----------------
__device__ __forceinline__ uint32_t smem_u32(const void* p) {
    uint32_t a;
    asm("{ .reg .u64 t; cvta.to.shared.u64 t, %1; cvt.u32.u64 %0, t; }" : "=r"(a) : "l"(p));
    return a;
}

#define CP_ASYNC16(dst, src) \
    asm volatile("cp.async.cg.shared.global [%0], [%1], 16;" :: "r"(dst), "l"(src))
#define CP_COMMIT() asm volatile("cp.async.commit_group;" ::: "memory")
#define CP_WAIT(n)  asm volatile("cp.async.wait_group %0;" :: "n"(n) : "memory")

#define LDSM4(r0, r1, r2, r3, addr) \
    asm volatile("ldmatrix.sync.aligned.m8n8.x4.shared.b16 {%0,%1,%2,%3}, [%4];" \
        : "=r"(r0), "=r"(r1), "=r"(r2), "=r"(r3) : "r"(addr))

#define MMA16816(d, a, b0, b1) \
    asm volatile("mma.sync.aligned.m16n8k16.row.col.f32.bf16.bf16.f32 " \
        "{%0,%1,%2,%3}, {%4,%5,%6,%7}, {%8,%9}, {%0,%1,%2,%3};" \
        : "+f"((d)[0]), "+f"((d)[1]), "+f"((d)[2]), "+f"((d)[3]) \
        : "r"((a)[0]), "r"((a)[1]), "r"((a)[2]), "r"((a)[3]), "r"(b0), "r"(b1))

__device__ __forceinline__ void split2(float x, __nv_bfloat16& h, __nv_bfloat16& l) {
    h = __float2bfloat16(x);
    l = __float2bfloat16(x - __bfloat162float(h));
}

// ============================================================
// Weight transpose + hi/lo split: src[K,N] fp32 -> dst[N,K] bf16 x2
// ============================================================
__device__ __forceinline__ void tsplit_body(
    const float* __restrict__ src, __nv_bfloat16* __restrict__ dh,
    __nv_bfloat16* __restrict__ dl, int K, int N)
{
    __shared__ float t[32][33];
    int n0 = blockIdx.x * 32, k0 = blockIdx.y * 32;
    int tx = threadIdx.x & 31, ty = threadIdx.x >> 5;
    #pragma unroll
    for (int j = 0; j < 32; j += 8)
        t[ty + j][tx] = src[(size_t)(k0 + ty + j) * N + n0 + tx];
    __syncthreads();
    #pragma unroll
    for (int j = 0; j < 32; j += 8) {
        float v = t[tx][ty + j];
        __nv_bfloat16 h, l; split2(v, h, l);
        size_t o = (size_t)(n0 + ty + j) * K + k0 + tx;
        dh[o] = h; dl[o] = l;
    }
}

__global__ __launch_bounds__(256) void tsplit_kernel(
    const float* __restrict__ src, __nv_bfloat16* __restrict__ dh,
    __nv_bfloat16* __restrict__ dl, int K, int N)
{
    tsplit_body(src, dh, dl, K, N);
}

// 3 square [EE,EE] weights -> one [QKVN,EE] split pair, z selects weight
__global__ __launch_bounds__(256) void tsplit_qkv_kernel(
    const float* __restrict__ wq, const float* __restrict__ wk,
    const float* __restrict__ wv, __nv_bfloat16* __restrict__ dh,
    __nv_bfloat16* __restrict__ dl)
{
    int z = blockIdx.z;
    const float* src = (z == 0) ? wq : (z == 1) ? wk : wv;
    tsplit_body(src, dh + (size_t)z * EE * EE, dl + (size_t)z * EE * EE, EE, EE);
}

// ============================================================
// LayerNorm (ddof=1) -> bf16 hi/lo outputs
// ============================================================
__global__ __launch_bounds__(256) void ln_kernel(
    const float* __restrict__ x, const float* __restrict__ sc,
    const float* __restrict__ sh, __nv_bfloat16* __restrict__ oh,
    __nv_bfloat16* __restrict__ ol)
{
    int row = blockIdx.x;
    int t = threadIdx.x;
    const float* xr = x + (size_t)row * EE;
    float v0 = xr[t], v1 = xr[t + 256], v2 = xr[t + 512];
    float s = v0 + v1 + v2, ss = v0*v0 + v1*v1 + v2*v2;
    #pragma unroll
    for (int o = 16; o; o >>= 1) {
        s  += __shfl_xor_sync(0xffffffffu, s,  o);
        ss += __shfl_xor_sync(0xffffffffu, ss, o);
    }
    __shared__ float red[2][8];
    __shared__ float mean_s, rstd_s;
    int w = t >> 5, ln = t & 31;
    if (ln == 0) { red[0][w] = s; red[1][w] = ss; }
    __syncthreads();
    if (t == 0) {
        float S = 0.f, SS = 0.f;
        #pragma unroll
        for (int i = 0; i < 8; i++) { S += red[0][i]; SS += red[1][i]; }
        float mean = S / (float)EE;
        float var  = (SS - S * mean) / (float)(EE - 1);
        mean_s = mean;
        rstd_s = rsqrtf(var + 1e-5f);
    }
    __syncthreads();
    float mean = mean_s, r = rstd_s;
    size_t base = (size_t)row * EE;
    #pragma unroll
    for (int u = 0; u < 3; u++) {
        int c = t + u * 256;
        float vv = (u == 0 ? v0 : (u == 1 ? v1 : v2));
        float y = sc[c] * (vv - mean) * r + sh[c];
        __nv_bfloat16 h, l; split2(y, h, l);
        oh[base + c] = h; ol[base + c] = l;
    }
}

// ============================================================
// mma.sync bf16 GEMM (3-way hi/lo split, fp32 accumulate)
// C[M,Nout] = A[M,K] @ B[Nout,K]^T
// CTA tile 128 x 128, K-chunk 64, cp.async 2-stage, 256 threads.
// Warps 4(M) x 2(N); warp tile 32 x 64; mma.m16n8k16.
// acc = 64 regs/thread -> no spills.
// EPI: 0 = fp32 | 1 = +bias +resid fp32 | 2 = +bias, GELU, bf16 hi/lo
// ============================================================
#define GBN 128
#define GWN 64                     // warp N extent
#define GNG 4                      // n16 groups per warp
#define GBSZ (GBN * 128)           // one B buffer (16 KB)
#define GSTAGE (32768 + 2 * GBSZ)  // Ah+Al (32K) + Bh+Bl (32K) = 64 KB
#define GEMM_SMEM (2 * GSTAGE)     // 128 KB

template<int EPI>
__global__ __launch_bounds__(256, 1) void mma_gemm(
    const __nv_bfloat16* __restrict__ Ahi, const __nv_bfloat16* __restrict__ Alo,
    const __nv_bfloat16* __restrict__ Bhi, const __nv_bfloat16* __restrict__ Blo,
    int K, int ldc,
    float* __restrict__ C,
    __nv_bfloat16* __restrict__ Chi, __nv_bfloat16* __restrict__ Clo,
    const float* __restrict__ bias, const float* __restrict__ resid)
{
    extern __shared__ char smc[];
    const int tid  = threadIdx.x;
    const int wid  = tid >> 5, lane = tid & 31;
    const int wm   = wid >> 1, wn = wid & 1;
    const uint32_t sbase = smem_u32(smc);
    const int rowBase = blockIdx.y * 128;
    const int colBase = blockIdx.x * GBN;
    const int nc = K / 64;

    // ---- async loader: gmem(bf16) -> swizzled smem stage ----
    auto load_stage = [&](int ch, int s) {
        const int kc = ch * 64;
        const uint32_t st = sbase + s * GSTAGE;
        int r = tid >> 3, c = tid & 7;
        uint32_t so = (uint32_t)(r * 128 + ((c ^ (r & 7)) * 16));
        #pragma unroll
        for (int j = 0; j < 4; j++) {                 // A: 128 rows x 8 chunks
            uint32_t soj = so + j * 4096;             // +32 rows
            size_t go = (size_t)(rowBase + r + j * 32) * K + kc + c * 8;
            CP_ASYNC16(st + soj,         Ahi + go);
            CP_ASYNC16(st + 16384 + soj, Alo + go);
        }
        #pragma unroll
        for (int j = 0; j < 4; j++) {                 // B: 128 rows x 8 chunks
            uint32_t soj = so + j * 4096;
            size_t go = (size_t)(colBase + r + j * 32) * K + kc + c * 8;
            CP_ASYNC16(st + 32768 + soj,        Bhi + go);
            CP_ASYNC16(st + 32768 + GBSZ + soj, Blo + go);
        }
    };

    float acc[2][GWN / 8][4];
    #pragma unroll
    for (int mi = 0; mi < 2; mi++)
        #pragma unroll
        for (int nj = 0; nj < GWN / 8; nj++)
            #pragma unroll
            for (int q = 0; q < 4; q++) acc[mi][nj][q] = 0.f;

    const uint32_t aoff = (uint32_t)((wm * 32 + (lane & 15)) * 128);
    const uint32_t boff = (uint32_t)((wn * GWN + (lane & 15)) * 128);
    const int csel = lane >> 4;
    const int cxor = lane & 7;

    load_stage(0, 0); CP_COMMIT();

    for (int ch = 0; ch < nc; ch++) {
        if (ch + 1 < nc) { load_stage(ch + 1, (ch + 1) & 1); CP_COMMIT(); CP_WAIT(1); }
        else             { CP_WAIT(0); }
        __syncthreads();

        const uint32_t stg = sbase + (ch & 1) * GSTAGE;
        #pragma unroll
        for (int p = 0; p < 3; p++) {    // AhBh, AhBl, AlBh
            const uint32_t Ab = stg + (p == 2 ? 16384 : 0);
            const uint32_t Bb = stg + 32768 + (p == 1 ? GBSZ : 0);
            #pragma unroll
            for (int k16 = 0; k16 < 4; k16++) {
                const uint32_t csw = (uint32_t)(((k16 * 2 + csel) ^ cxor) * 16);
                uint32_t a[2][4];
                LDSM4(a[0][0], a[0][1], a[0][2], a[0][3], Ab + aoff + csw);
                LDSM4(a[1][0], a[1][1], a[1][2], a[1][3], Ab + aoff + 2048 + csw);
                #pragma unroll
                for (int ng = 0; ng < GNG; ng++) {
                    uint32_t b0, b1, b2, b3;
                    LDSM4(b0, b1, b2, b3, Bb + boff + ng * 2048 + csw);
                    MMA16816(acc[0][2 * ng],     a[0], b0, b2);
                    MMA16816(acc[0][2 * ng + 1], a[0], b1, b3);
                    MMA16816(acc[1][2 * ng],     a[1], b0, b2);
                    MMA16816(acc[1][2 * ng + 1], a[1], b1, b3);
                }
            }
        }
        __syncthreads();
    }

    // ---- epilogue ----
    const int lr = lane >> 2, lc = (lane & 3) * 2;
    #pragma unroll
    for (int mi = 0; mi < 2; mi++) {
        #pragma unroll
        for (int nj = 0; nj < GWN / 8; nj++) {
            int r0 = rowBase + wm * 32 + mi * 16 + lr;
            int c0 = colBase + wn * GWN + nj * 8 + lc;
            float* d = acc[mi][nj];
            #pragma unroll
            for (int half = 0; half < 2; half++) {
                int r = r0 + half * 8;
                float v0 = d[half * 2], v1 = d[half * 2 + 1];
                if (EPI >= 1) { v0 += bias[c0]; v1 += bias[c0 + 1]; }
                if (EPI == 2) {
                    float u0 = v0, u1 = v1;
                    v0 = 0.5f * u0 * (1.f + tanhf(0.7978845608028654f * (u0 + 0.044715f * u0 * u0 * u0)));
                    v1 = 0.5f * u1 * (1.f + tanhf(0.7978845608028654f * (u1 + 0.044715f * u1 * u1 * u1)));
                }
                if (EPI == 1) {
                    v0 += resid[(size_t)r * ldc + c0];
                    v1 += resid[(size_t)r * ldc + c0 + 1];
                }
                if (EPI == 2) {
                    __nv_bfloat16 h0, l0, h1, l1;
                    split2(v0, h0, l0); split2(v1, h1, l1);
                    *(__nv_bfloat162*)&Chi[(size_t)r * ldc + c0] = __nv_bfloat162(h0, h1);
                    *(__nv_bfloat162*)&Clo[(size_t)r * ldc + c0] = __nv_bfloat162(l0, l1);
                } else {
                    *(float2*)&C[(size_t)r * ldc + c0] = make_float2(v0, v1);
                }
            }
        }
    }
}

// ============================================================
// Causal flash attention, fp32, fused-QKV input, hi/lo ctx output
// ============================================================
__global__ __launch_bounds__(128) void attn_kernel(
    const float* __restrict__ qkv, __nv_bfloat16* __restrict__ cxh,
    __nv_bfloat16* __restrict__ cxl)
{
    __shared__ float Qt[64][128];
    __shared__ float Ks[32][64];
    __shared__ float Vs[32][64];

    int tid = threadIdx.x;
    int bh = blockIdx.y;
    int b = bh / HH, h = bh % HH;
    int q0 = blockIdx.x * 128;
    const float* qb = qkv + (size_t)b * TT * QKVN + h * DD;
    const float* kb = qb + EE;
    const float* vb = qb + 2 * EE;
    const float SC = 0.125f * 1.4426950408889634f;

    for (int i = tid; i < 128 * 64; i += 128) {
        int rr = i >> 6, dd = i & 63;
        Qt[dd][rr] = qb[(size_t)(q0 + rr) * QKVN + dd] * SC;
    }

    float O[64];
    #pragma unroll
    for (int d = 0; d < 64; d++) O[d] = 0.f;
    float m = -1e30f, l = 0.f;
    int qi = q0 + tid;
    int ktiles = q0 / 32 + 4;

    for (int jt = 0; jt < ktiles; ++jt) {
        int k0 = jt * 32;
        __syncthreads();
        for (int i = tid; i < 32 * 64; i += 128) {
            int rr = i >> 6, dd = i & 63;
            Ks[rr][dd] = kb[(size_t)(k0 + rr) * QKVN + dd];
            Vs[rr][dd] = vb[(size_t)(k0 + rr) * QKVN + dd];
        }
        __syncthreads();

        float s[32];
        #pragma unroll
        for (int c = 0; c < 32; c++) s[c] = 0.f;
        #pragma unroll
        for (int d0 = 0; d0 < 64; d0 += 4) {
            float q0v = Qt[d0][tid],     q1v = Qt[d0 + 1][tid];
            float q2v = Qt[d0 + 2][tid], q3v = Qt[d0 + 3][tid];
            #pragma unroll
            for (int c = 0; c < 32; c++) {
                const float4 kv = *(const float4*)&Ks[c][d0];
                s[c] += q0v * kv.x + q1v * kv.y + q2v * kv.z + q3v * kv.w;
            }
        }

        float mloc = -1e30f;
        #pragma unroll
        for (int c = 0; c < 32; c++) {
            if (k0 + c > qi) s[c] = -1e30f;
            mloc = fmaxf(mloc, s[c]);
        }
        float mn  = fmaxf(m, mloc);
        float fac = exp2f(m - mn);
        l *= fac;
        #pragma unroll
        for (int d = 0; d < 64; d++) O[d] *= fac;
        #pragma unroll
        for (int c = 0; c < 32; c++) {
            float p = exp2f(s[c] - mn);
            l += p;
            #pragma unroll
            for (int d0 = 0; d0 < 64; d0 += 4) {
                const float4 vv = *(const float4*)&Vs[c][d0];
                O[d0]     += p * vv.x;
                O[d0 + 1] += p * vv.y;
                O[d0 + 2] += p * vv.z;
                O[d0 + 3] += p * vv.w;
            }
        }
        m = mn;
    }

    float inv = 1.f / l;
    size_t ob = (size_t)(b * TT + q0 + tid) * EE + h * DD;
    #pragma unroll
    for (int d = 0; d < 64; d++) {
        __nv_bfloat16 hh, ll;
        split2(O[d] * inv, hh, ll);
        cxh[ob + d] = hh; cxl[ob + d] = ll;
    }
}

// ============================================================
extern "C" void kernel_launch(void* const* d_in, const int* in_sizes, int n_in,
                              void* d_out, int out_size)
{
    const float* x   = (const float*)d_in[0];
    const float* wq  = (const float*)d_in[1];
    const float* wk  = (const float*)d_in[2];
    const float* wv  = (const float*)d_in[3];
    const float* wo  = (const float*)d_in[4];
    const float* bo  = (const float*)d_in[5];
    const float* l1s = (const float*)d_in[6];
    const float* l1b = (const float*)d_in[7];
    const float* l2s = (const float*)d_in[8];
    const float* l2b = (const float*)d_in[9];
    const float* w1  = (const float*)d_in[10];
    const float* b1  = (const float*)d_in[11];
    const float* w2  = (const float*)d_in[12];
    const float* b2  = (const float*)d_in[13];
    float* out = (float*)d_out;

    float *qkv, *x1;
    __nv_bfloat16 *h1h,*h1l,*h2h,*h2l,*cxh,*cxl,*f1h,*f1l;
    __nv_bfloat16 *wqkvh,*wqkvl,*woh,*wol,*w1h,*w1l,*w2h,*w2l;
    cudaGetSymbolAddress((void**)&qkv, g_qkv);
    cudaGetSymbolAddress((void**)&x1,  g_x1);
    cudaGetSymbolAddress((void**)&h1h, g_h1h); cudaGetSymbolAddress((void**)&h1l, g_h1l);
    cudaGetSymbolAddress((void**)&h2h, g_h2h); cudaGetSymbolAddress((void**)&h2l, g_h2l);
    cudaGetSymbolAddress((void**)&cxh, g_cxh); cudaGetSymbolAddress((void**)&cxl, g_cxl);
    cudaGetSymbolAddress((void**)&f1h, g_f1h); cudaGetSymbolAddress((void**)&f1l, g_f1l);
    cudaGetSymbolAddress((void**)&wqkvh, g_wqkvh); cudaGetSymbolAddress((void**)&wqkvl, g_wqkvl);
    cudaGetSymbolAddress((void**)&woh, g_woh); cudaGetSymbolAddress((void**)&wol, g_wol);
    cudaGetSymbolAddress((void**)&w1h, g_w1h); cudaGetSymbolAddress((void**)&w1l, g_w1l);
    cudaGetSymbolAddress((void**)&w2h, g_w2h); cudaGetSymbolAddress((void**)&w2l, g_w2l);

    cudaFuncSetAttribute(mma_gemm<0>, cudaFuncAttributeMaxDynamicSharedMemorySize, GEMM_SMEM);
    cudaFuncSetAttribute(mma_gemm<1>, cudaFuncAttributeMaxDynamicSharedMemorySize, GEMM_SMEM);
    cudaFuncSetAttribute(mma_gemm<2>, cudaFuncAttributeMaxDynamicSharedMemorySize, GEMM_SMEM);

    // ---- prep: transpose + split weights (4 launches) ----
    tsplit_qkv_kernel<<<dim3(EE/32, EE/32, 3), 256>>>(wq, wk, wv, wqkvh, wqkvl);  // 1
    tsplit_kernel<<<dim3(EE/32, EE/32), 256>>>(wo, woh, wol, EE, EE);             // 2
    tsplit_kernel<<<dim3(FFN/32, EE/32), 256>>>(w1, w1h, w1l, EE, FFN);           // 3
    tsplit_kernel<<<dim3(EE/32, FFN/32), 256>>>(w2, w2h, w2l, FFN, EE);           // 4

    // ---- LN1 -> h1 (bf16 hi/lo) ----                                            // 5
    ln_kernel<<<MM, 256>>>(x, l1s, l1b, h1h, h1l);
    // ---- fused QKV GEMM (launch #6 -> ncu capture target) ----
    mma_gemm<0><<<dim3(QKVN/GBN, MM/128), 256, GEMM_SMEM>>>(
        h1h, h1l, wqkvh, wqkvl, EE, QKVN, qkv, nullptr, nullptr, nullptr, nullptr);
    // ---- attention -> ctx (bf16 hi/lo) ----
    attn_kernel<<<dim3(TT/128, BB*HH), 128>>>(qkv, cxh, cxl);
    // ---- WO proj + bias + resid(x) -> x1 fp32 ----
    mma_gemm<1><<<dim3(EE/GBN, MM/128), 256, GEMM_SMEM>>>(
        cxh, cxl, woh, wol, EE, EE, x1, nullptr, nullptr, bo, x);
    // ---- LN2 -> h2 (bf16 hi/lo) ----
    ln_kernel<<<MM, 256>>>(x1, l2s, l2b, h2h, h2l);
    // ---- MLP up + GELU -> f1 (bf16 hi/lo) ----
    mma_gemm<2><<<dim3(FFN/GBN, MM/128), 256, GEMM_SMEM>>>(
        h2h, h2l, w1h, w1l, EE, FFN, nullptr, f1h, f1l, b1, nullptr);
    // ---- MLP down + bias + resid(x1) -> out ----
    mma_gemm<1><<<dim3(EE/GBN, MM/128), 256, GEMM_SMEM>>>(
        f1h, f1l, w2h, w2l, FFN, EE, out, nullptr, nullptr, b2, x1);
}